// round 16
// baseline (speedup 1.0000x reference)
#include <cuda_runtime.h>

// Causal depthwise conv1d: out[b,t,c] = bias[c] + sum_k w[k,0,c] * x[b, t-(K-1)+k, c]
// x (4, 8192, 2048) f32, weight (4,1,2048), bias (2048). NHC layout.
//
// Round-16 experiment: Blackwell 256-bit global accesses (ld.global.nc.v8.f32 /
// st.global.cs.v8.f32). Same DRAM sectors as the converged 128-bit kernel, but
// half the LSU issue slots and half the L1tex wavefront-queue entries per byte.
// Thread owns 8 consecutive channels; TB=128 -> identical 4096-CTA grid shape
// to the record kernel. TPT=16, CHNK=2 (64B in flight per chunk, same as best).

constexpr int B    = 4;
constexpr int T    = 8192;
constexpr int C    = 2048;
constexpr int C8   = C / 8;      // 256 float8 lanes per timestep
constexpr int TPT  = 16;         // timesteps per thread
constexpr int CHNK = 2;          // 256-bit loads batched per chunk
constexpr int TB   = 128;        // threads per block

__device__ __forceinline__ void ldg256(const float* __restrict__ p, float r[8]) {
    asm volatile("ld.global.nc.v8.f32 {%0,%1,%2,%3,%4,%5,%6,%7}, [%8];"
                 : "=f"(r[0]), "=f"(r[1]), "=f"(r[2]), "=f"(r[3]),
                   "=f"(r[4]), "=f"(r[5]), "=f"(r[6]), "=f"(r[7])
                 : "l"(p));
}

__device__ __forceinline__ void stg256_cs(float* p, const float r[8]) {
    asm volatile("st.global.cs.v8.f32 [%0], {%1,%2,%3,%4,%5,%6,%7,%8};"
                 :: "l"(p),
                    "f"(r[0]), "f"(r[1]), "f"(r[2]), "f"(r[3]),
                    "f"(r[4]), "f"(r[5]), "f"(r[6]), "f"(r[7])
                 : "memory");
}

__global__ __launch_bounds__(TB)
void causal_conv1d_kernel(const float* __restrict__ x,
                          const float* __restrict__ w,
                          const float* __restrict__ bias,
                          float* __restrict__ out)
{
    const int c8 = blockIdx.x * TB + threadIdx.x;   // 0..C8-1
    const int t0 = blockIdx.y * TPT;
    const int b  = blockIdx.z;
    const int c  = c8 * 8;                          // first channel of this thread

    // Depthwise weights: w[k][0][c] at w[k*C + c]
    float w0[8], w1[8], w2[8], w3[8], bs[8];
    ldg256(w + 0 * C + c, w0);
    ldg256(w + 1 * C + c, w1);
    ldg256(w + 2 * C + c, w2);
    ldg256(w + 3 * C + c, w3);
    ldg256(bias + c, bs);

    const float* xp = x   + (size_t)b * T * C + c;
    float*       op = out + (size_t)b * T * C + c;

    // Sliding window: x[t-3], x[t-2], x[t-1]
    float xm3[8], xm2[8], xm1[8];
    if (t0 == 0) {
#pragma unroll
        for (int j = 0; j < 8; ++j) { xm3[j] = 0.f; xm2[j] = 0.f; xm1[j] = 0.f; }
    } else {
        ldg256(xp + (size_t)(t0 - 3) * C, xm3);
        ldg256(xp + (size_t)(t0 - 2) * C, xm2);
        ldg256(xp + (size_t)(t0 - 1) * C, xm1);
    }

#pragma unroll
    for (int ch = 0; ch < TPT / CHNK; ++ch) {
        const int tc = t0 + ch * CHNK;

        // Batch independent 256-bit loads before any dependent math.
        float xa[CHNK][8];
#pragma unroll
        for (int i = 0; i < CHNK; ++i)
            ldg256(xp + (size_t)(tc + i) * C, xa[i]);

        float oa[CHNK][8];
#pragma unroll
        for (int i = 0; i < CHNK; ++i) {
#pragma unroll
            for (int j = 0; j < 8; ++j) {
                oa[i][j] = bs[j] + w0[j] * xm3[j] + w1[j] * xm2[j]
                                 + w2[j] * xm1[j] + w3[j] * xa[i][j];
            }
#pragma unroll
            for (int j = 0; j < 8; ++j) {
                xm3[j] = xm2[j];
                xm2[j] = xm1[j];
                xm1[j] = xa[i][j];
            }
        }

        // 256-bit streaming stores: evict-first, out is write-once.
#pragma unroll
        for (int i = 0; i < CHNK; ++i)
            stg256_cs(op + (size_t)(tc + i) * C, oa[i]);
    }
}

extern "C" void kernel_launch(void* const* d_in, const int* in_sizes, int n_in,
                              void* d_out, int out_size)
{
    const float* x    = (const float*)d_in[0];
    const float* w    = (const float*)d_in[1];
    const float* bias = (const float*)d_in[2];
    float*       out  = (float*)d_out;

    dim3 grid(C8 / TB, T / TPT, B);   // (2, 512, 4)
    causal_conv1d_kernel<<<grid, TB>>>(x, w, bias, out);
}